// round 4
// baseline (speedup 1.0000x reference)
#include <cuda_runtime.h>

#define N_BATCH 4
#define C_CH    256
#define H_DIM   96
#define W_DIM   96
#define HW      (H_DIM * W_DIM)
#define OUTS    7
#define BINS    (OUTS * OUTS)     // 49
#define G_SAMP  (OUTS * 2)        // 14 sample coords per axis
#define SPATIAL_SCALE 0.0625f
#define CPB     128               // channels per block

// Scratch: NHWC-transposed features (b, h, w, c)
__device__ float g_featT[(size_t)N_BATCH * HW * C_CH];

// ---------------------------------------------------------------------------
// Transpose (N, C, HW) -> (N, HW, C), classic 32x32 smem tile.
// Grid: (HW/32, C/32, N), Block: (32, 8)
// ---------------------------------------------------------------------------
__global__ void nchw_to_nhwc(const float* __restrict__ in) {
    __shared__ float tile[32][33];
    const int n   = blockIdx.z;
    const int hw0 = blockIdx.x * 32;
    const int c0  = blockIdx.y * 32;
    const float* inp = in + (size_t)n * C_CH * HW;
    float* op = g_featT + (size_t)n * HW * C_CH;

    const int x = hw0 + threadIdx.x;           // hw index (contiguous read)
#pragma unroll
    for (int j = 0; j < 32; j += 8) {
        const int cc = c0 + threadIdx.y + j;
        tile[threadIdx.y + j][threadIdx.x] = inp[(size_t)cc * HW + x];
    }
    __syncthreads();
    const int cx = c0 + threadIdx.x;           // channel (contiguous write)
#pragma unroll
    for (int j = 0; j < 32; j += 8) {
        const int hh = hw0 + threadIdx.y + j;
        op[(size_t)hh * C_CH + cx] = tile[threadIdx.x][threadIdx.y + j];
    }
}

// ---------------------------------------------------------------------------
// RoI Align main kernel.
// Grid: (C/CPB, K). Block: CPB threads, thread = channel within half.
// Per-roi 1D sample tables (flattened offsets + weights, invalid -> w=0)
// in smem; staged output in smem for coalesced writeback.
// ---------------------------------------------------------------------------
__global__ __launch_bounds__(CPB) void roi_align_kernel(
    const float* __restrict__ rois,
    float* __restrict__ out)
{
    __shared__ int   s_ylo[G_SAMP], s_yhi[G_SAMP];   // (b*H+y)*W*C  premultiplied
    __shared__ float s_wyl[G_SAMP], s_wyh[G_SAMP];
    __shared__ int   s_xlo[G_SAMP], s_xhi[G_SAMP];   // x*C premultiplied
    __shared__ float s_wxl[G_SAMP], s_wxh[G_SAMP];
    __shared__ float stage[CPB * BINS];              // 25088 B

    const int k     = blockIdx.y;
    const int cbase = blockIdx.x * CPB;
    const int tid   = threadIdx.x;

    if (tid < 2 * G_SAMP) {
        const int axis = tid / G_SAMP;   // 0 = y, 1 = x
        const int g    = tid % G_SAMP;
        const float* r = rois + (size_t)k * 5;
        const int   b  = (int)r[0];
        const float x1 = r[1] * SPATIAL_SCALE;
        const float y1 = r[2] * SPATIAL_SCALE;
        const float x2 = r[3] * SPATIAL_SCALE;
        const float y2 = r[4] * SPATIAL_SCALE;

        float start, binsz;
        if (axis == 0) { start = y1; binsz = fmaxf(y2 - y1, 1.0f) * (1.0f / OUTS); }
        else           { start = x1; binsz = fmaxf(x2 - x1, 1.0f) * (1.0f / OUTS); }

        const float off   = (float)(g >> 1) + 0.25f + 0.5f * (float)(g & 1);
        const float coord = fmaf(binsz, off, start);
        const bool  valid = (coord >= -1.0f) && (coord <= 96.0f);
        const float cc    = fminf(fmaxf(coord, 0.0f), 95.0f);
        const float lof   = floorf(cc);
        const int   lo    = (int)lof;
        const int   hi    = min(lo + 1, 95);
        const float fr    = cc - lof;
        const float wl    = valid ? 1.0f - fr : 0.0f;
        const float wh    = valid ? fr        : 0.0f;

        if (axis == 0) {
            s_ylo[g] = (b * H_DIM + lo) * W_DIM * C_CH;
            s_yhi[g] = (b * H_DIM + hi) * W_DIM * C_CH;
            s_wyl[g] = wl; s_wyh[g] = wh;
        } else {
            s_xlo[g] = lo * C_CH;
            s_xhi[g] = hi * C_CH;
            s_wxl[g] = wl; s_wxh[g] = wh;
        }
    }
    __syncthreads();

    const float* fc = g_featT + cbase + tid;     // per-thread channel pointer

#pragma unroll
    for (int i = 0; i < OUTS; i++) {
        const int gy0 = 2 * i, gy1 = 2 * i + 1;
        const int   y0l = s_ylo[gy0], y0h = s_yhi[gy0];
        const int   y1l = s_ylo[gy1], y1h = s_yhi[gy1];
        const float wy0l = s_wyl[gy0], wy0h = s_wyh[gy0];
        const float wy1l = s_wyl[gy1], wy1h = s_wyh[gy1];

#pragma unroll
        for (int j = 0; j < OUTS; j++) {
            float acc = 0.0f;
#pragma unroll
            for (int sx = 0; sx < 2; sx++) {
                const int gx = 2 * j + sx;
                const int   xl  = s_xlo[gx], xh = s_xhi[gx];
                const float wxl = s_wxl[gx], wxh = s_wxh[gx];

                // sample (gy0, gx)
                const float a00 = __ldg(fc + y0l + xl);
                const float a01 = __ldg(fc + y0l + xh);
                const float a10 = __ldg(fc + y0h + xl);
                const float a11 = __ldg(fc + y0h + xh);
                acc += wy0l * (wxl * a00 + wxh * a01)
                     + wy0h * (wxl * a10 + wxh * a11);

                // sample (gy1, gx)
                const float b00 = __ldg(fc + y1l + xl);
                const float b01 = __ldg(fc + y1l + xh);
                const float b10 = __ldg(fc + y1h + xl);
                const float b11 = __ldg(fc + y1h + xh);
                acc += wy1l * (wxl * b00 + wxh * b01)
                     + wy1h * (wxl * b10 + wxh * b11);
            }
            stage[tid * BINS + i * OUTS + j] = acc * 0.25f;
        }
    }
    __syncthreads();

    // Coalesced writeback: this block owns 128*49 consecutive floats of out.
    float* outp = out + ((size_t)k * C_CH + cbase) * BINS;
    for (int t = tid; t < CPB * BINS; t += CPB)
        outp[t] = stage[t];
}

extern "C" void kernel_launch(void* const* d_in, const int* in_sizes, int n_in,
                              void* d_out, int out_size) {
    const float* features = (const float*)d_in[0];
    const float* rois     = (const float*)d_in[1];
    float* out            = (float*)d_out;
    const int K = in_sizes[1] / 5;

    // 1) NCHW -> NHWC transpose into scratch
    nchw_to_nhwc<<<dim3(HW / 32, C_CH / 32, N_BATCH), dim3(32, 8)>>>(features);

    // 2) RoI Align gather, fully coalesced along channels
    roi_align_kernel<<<dim3(C_CH / CPB, K), CPB>>>(rois, out);
}